// round 14
// baseline (speedup 1.0000x reference)
#include <cuda_runtime.h>
#include <cuda_bf16.h>
#include <cstdint>

#define Bb 64
#define Tt 512
#define Ii 1024
#define Hh 1024

#define FUSED_CTAS 128
#define TOTAL_CTAS 148
#define XP_TILES 2048         // 16 blk * (16 bq * 8 nb)
#define XP_BLKS 16
#define XP_TILES_PER_BLK 128

// smem floats: rnn (Wsh 32768 + hs 16384 + red 8*576=4608)
//            + xproj role-B buffers (2*2112) + 16 scheduler slots
#define RNN_FLOATS (32768 + 16384 + 4608)
#define XP_ROLE_FLOATS (2 * 16 * 132)
#define SMEM_BYTES ((RNN_FLOATS + XP_ROLE_FLOATS + 16) * 4)   // 232,000 B

__device__ __align__(16) float g_Wih[Hh * Ii];
__device__ __align__(16) float g_bias[Hh];
__device__ __align__(16) float g_hT[2 * Hh * Bb];   // double-buffered h, [k][b]
__device__ unsigned g_cnt[128];     // 4 h-barrier domains, stride 32
__device__ unsigned g_xcnt[XP_BLKS];// xproj per-t-block completion counters
__device__ unsigned g_xtask;        // dynamic xproj tile counter
__device__ unsigned g_done;

typedef unsigned long long u64t;

__device__ __forceinline__ u64t pack2(float x, float y) {
    u64t r; asm("mov.b64 %0, {%1,%2};" : "=l"(r) : "f"(x), "f"(y)); return r;
}
__device__ __forceinline__ u64t fma2(u64t a, u64t b, u64t c) {
    u64t d; asm("fma.rn.f32x2 %0, %1, %2, %3;" : "=l"(d) : "l"(a), "l"(b), "l"(c)); return d;
}
__device__ __forceinline__ u64t add2(u64t a, u64t b) {
    u64t d; asm("add.rn.f32x2 %0, %1, %2;" : "=l"(d) : "l"(a), "l"(b)); return d;
}
__device__ __forceinline__ void cpasync16(uint32_t dst, const void* src) {
    asm volatile("cp.async.cg.shared.global [%0], [%1], 16;" :: "r"(dst), "l"(src));
}
#define CP_COMMIT() asm volatile("cp.async.commit_group;")
#define BARX(id) asm volatile("bar.sync %0, %1;" :: "r"(id), "r"(256) : "memory")

__device__ __forceinline__ void arrive_release(unsigned* p) {
    asm volatile("red.release.gpu.global.add.u32 [%0], %1;" :: "l"(p), "r"(1u) : "memory");
}
__device__ __forceinline__ unsigned ld_acquire(unsigned* p) {
    unsigned v;
    asm volatile("ld.acquire.gpu.global.u32 %0, [%1];" : "=r"(v) : "l"(p) : "memory");
    return v;
}

__device__ __forceinline__ float hc_gate(float x) {
    float s = 1.0f / (1.0f + expf(-x));
    float v = s * 1.2f - 0.1f;
    return fminf(fmaxf(v, 0.0f), 1.0f);
}

// ---------------------------------------------------------------------------
// Phase 1: gate Wih + bias, zero h0, reset counters
// ---------------------------------------------------------------------------
__global__ void regrnn_prep(const float* __restrict__ w_ih, const float* __restrict__ w_ih_mask,
                            const float* __restrict__ b_ih, const float* __restrict__ b_ih_mask,
                            const float* __restrict__ b_hh, const float* __restrict__ b_hh_mask) {
    int i = blockIdx.x * blockDim.x + threadIdx.x;
    if (i < Hh * Ii) {
        g_Wih[i] = hc_gate(w_ih_mask[i]) * w_ih[i];
    }
    if (i < Hh) {
        g_bias[i] = hc_gate(b_ih_mask[i]) * b_ih[i] + hc_gate(b_hh_mask[i]) * b_hh[i];
    }
    if (i < 2 * Hh * Bb) g_hT[i] = 0.0f;
    if (i < 128) g_cnt[i] = 0u;
    if (i < XP_BLKS) g_xcnt[i] = 0u;
    if (i == 0) { g_xtask = 0u; g_done = 0u; }
}

// ---------------------------------------------------------------------------
// xproj role with DYNAMIC tile scheduling: rtid 0 fetches the next tile id
// from a global atomic counter and broadcasts via a dedicated smem slot.
// Tile = (4 batches x 32 timesteps) x 128 n, global counter keeps t-block
// order monotonic -> g_xcnt gating semantics unchanged.
// ---------------------------------------------------------------------------
__device__ void xproj_role(int rtid, int bid, float* As, float* Bs,
                           volatile unsigned* slot,
                           const float* __restrict__ A, float* __restrict__ out)
{
    const int wrole = rtid >> 5;
    const int lane = rtid & 31;
    const int ty = ((wrole & 1) << 3) + (lane >> 2);   // m-octet 0..15
    const int tx = ((wrole >> 1) << 2) + (lane & 3);   // n-octet 0..15

    const int i0 = rtid >> 2;
    const int k4 = (rtid & 3) << 2;
    const int i1 = i0 + 64;

    for (;;) {
        if (rtid == 0) *slot = atomicAdd(&g_xtask, 1u);
        BARX(bid);
        const unsigned tau = *slot;
        if (tau >= XP_TILES) break;

        const int blk = tau >> 7;
        const int r = tau & 127;
        const int b0 = (r >> 3) << 2;
        const int n0 = (r & 7) << 7;
        const int t0 = blk << 5;

        const int mrow0 = (b0 + (i0 >> 5)) * Tt + t0 + (i0 & 31);
        const int mrow1 = (b0 + (i1 >> 5)) * Tt + t0 + (i1 & 31);
        const float* pA0 = A + (size_t)mrow0 * Ii + k4;
        const float* pA1 = A + (size_t)mrow1 * Ii + k4;
        const float* pB0 = g_Wih + (size_t)(n0 + i0) * Ii + k4;
        const float* pB1 = g_Wih + (size_t)(n0 + i1) * Ii + k4;

        u64t acc[8][4];
#pragma unroll
        for (int i = 0; i < 8; i++)
#pragma unroll
            for (int j = 0; j < 4; j++) acc[i][j] = 0ULL;

        float4 a0v = *(const float4*)(pA0);
        float4 a1v = *(const float4*)(pA1);
        float4 b0v = *(const float4*)(pB0);
        float4 b1v = *(const float4*)(pB1);

        for (int kt = 0; kt < Ii; kt += 16) {
            As[(k4 + 0) * 132 + i0] = a0v.x; As[(k4 + 1) * 132 + i0] = a0v.y;
            As[(k4 + 2) * 132 + i0] = a0v.z; As[(k4 + 3) * 132 + i0] = a0v.w;
            As[(k4 + 0) * 132 + i1] = a1v.x; As[(k4 + 1) * 132 + i1] = a1v.y;
            As[(k4 + 2) * 132 + i1] = a1v.z; As[(k4 + 3) * 132 + i1] = a1v.w;
            Bs[(k4 + 0) * 132 + i0] = b0v.x; Bs[(k4 + 1) * 132 + i0] = b0v.y;
            Bs[(k4 + 2) * 132 + i0] = b0v.z; Bs[(k4 + 3) * 132 + i0] = b0v.w;
            Bs[(k4 + 0) * 132 + i1] = b1v.x; Bs[(k4 + 1) * 132 + i1] = b1v.y;
            Bs[(k4 + 2) * 132 + i1] = b1v.z; Bs[(k4 + 3) * 132 + i1] = b1v.w;
            BARX(bid);

            if (kt + 16 < Ii) {
                a0v = *(const float4*)(pA0 + kt + 16);
                a1v = *(const float4*)(pA1 + kt + 16);
                b0v = *(const float4*)(pB0 + kt + 16);
                b1v = *(const float4*)(pB1 + kt + 16);
            }

#pragma unroll
            for (int kk = 0; kk < 16; kk++) {
                float4 a0 = *(const float4*)&As[kk * 132 + (ty << 3)];
                float4 a1 = *(const float4*)&As[kk * 132 + (ty << 3) + 4];
                ulonglong2 b01 = *(const ulonglong2*)&Bs[kk * 132 + (tx << 3)];
                ulonglong2 b23 = *(const ulonglong2*)&Bs[kk * 132 + (tx << 3) + 4];
                float am[8] = {a0.x, a0.y, a0.z, a0.w, a1.x, a1.y, a1.z, a1.w};
#pragma unroll
                for (int mi = 0; mi < 8; mi++) {
                    u64t s = pack2(am[mi], am[mi]);
                    acc[mi][0] = fma2(s, b01.x, acc[mi][0]);
                    acc[mi][1] = fma2(s, b01.y, acc[mi][1]);
                    acc[mi][2] = fma2(s, b23.x, acc[mi][2]);
                    acc[mi][3] = fma2(s, b23.y, acc[mi][3]);
                }
            }
            BARX(bid);
        }

        const int n = n0 + (tx << 3);
        ulonglong2 bv0 = *(const ulonglong2*)(g_bias + n);
        ulonglong2 bv1 = *(const ulonglong2*)(g_bias + n + 4);
#pragma unroll
        for (int i = 0; i < 8; i++) {
            int mi = (ty << 3) + i;
            int mrow = (b0 + (mi >> 5)) * Tt + t0 + (mi & 31);
            ulonglong2 st0, st1;
            st0.x = add2(acc[i][0], bv0.x); st0.y = add2(acc[i][1], bv0.y);
            st1.x = add2(acc[i][2], bv1.x); st1.y = add2(acc[i][3], bv1.y);
            *(ulonglong2*)(out + (size_t)mrow * Hh + n) = st0;
            *(ulonglong2*)(out + (size_t)mrow * Hh + n + 4) = st1;
        }
        BARX(bid);
        if (rtid == 0) arrive_release(&g_xcnt[blk]);
    }
}

// ---------------------------------------------------------------------------
// rnn role (unchanged from R13 winner): 8 warps, K-split 8 with intra-warp
// 2-way k-split + shfl combine; padded [b][c] partials.
// ---------------------------------------------------------------------------
__device__ void rnn_role(int t, int cta,
                         const float* __restrict__ w_hh, const float* __restrict__ w_hh_mask,
                         float* __restrict__ out, float* sm)
{
    float* Wsh = sm;                    // [1024][32]
    float* hsAll = sm + 32768;          // [8 warps][4 rounds][32 k][16 b]
    float* red = sm + 32768 + 16384;    // [8][16 b][36]

    const int w = t >> 5;
    const int lane = t & 31;
    const int cg = cta >> 2;
    const int bg = cta & 3;
    const int C0 = cg * 32;
    const int B0 = bg * 16;

    for (int i = t; i < 8192; i += 256) {
        int c = i & 31;
        int k4 = (i >> 5) << 2;
        size_t base = (size_t)(C0 + c) * Ii + k4;
        float4 wv = *(const float4*)(w_hh + base);
        float4 mv = *(const float4*)(w_hh_mask + base);
        Wsh[(k4 + 0) * 32 + c] = hc_gate(mv.x) * wv.x;
        Wsh[(k4 + 1) * 32 + c] = hc_gate(mv.y) * wv.y;
        Wsh[(k4 + 2) * 32 + c] = hc_gate(mv.z) * wv.z;
        Wsh[(k4 + 3) * 32 + c] = hc_gate(mv.w) * wv.w;
    }

    const int ksub = lane >> 4;
    const int tile = lane & 15;
    const int cq = tile >> 2;
    const int bq = tile & 3;

    float* hw = hsAll + w * 2048;
    uint32_t hw_u32 = (uint32_t)__cvta_generic_to_shared(hw);
    const int kbase = ((w + cg) & 7) * 128;

    const int c_l = t >> 3;
    const int b2 = (t & 7) << 1;
    const int c_g = C0 + c_l;

    unsigned* cnt = &g_cnt[bg * 32];

    int xi0 = ((B0 + b2) * Tt) * Hh + c_g;
    int xi1 = ((B0 + b2 + 1) * Tt) * Hh + c_g;

    if (t == 0) {
        while (ld_acquire(&g_xcnt[0]) < XP_TILES_PER_BLK) { }
    }
    BARX(1);

    for (int step = 0; step < Tt; step++) {
        const float* hsrc = g_hT + (step & 1) * (Hh * Bb);
        float* hdst = g_hT + ((step & 1) ^ 1) * (Hh * Bb);

#pragma unroll
        for (int r = 0; r < 4; r++) {
#pragma unroll
            for (int i = 0; i < 4; i++) {
                int fid = lane + (i << 5);
                int kk = fid >> 2;
                int c4 = (fid & 3) << 2;
                cpasync16(hw_u32 + ((r * 512 + kk * 16 + c4) << 2),
                          hsrc + (kbase + r * 32 + kk) * Bb + B0 + c4);
            }
            CP_COMMIT();
        }

        float xp0 = __ldcg(out + xi0);
        float xp1 = __ldcg(out + xi1);

        u64t acc[4][4];
#pragma unroll
        for (int i = 0; i < 4; i++)
#pragma unroll
            for (int j = 0; j < 4; j++) acc[i][j] = 0ULL;

#pragma unroll
        for (int r = 0; r < 4; r++) {
            switch (r) {
                case 0: asm volatile("cp.async.wait_group 3;"); break;
                case 1: asm volatile("cp.async.wait_group 2;"); break;
                case 2: asm volatile("cp.async.wait_group 1;"); break;
                default: asm volatile("cp.async.wait_group 0;"); break;
            }
            __syncwarp();
            const float* hb = hw + r * 512;
            const int kr = kbase + r * 32;
#pragma unroll
            for (int i = 0; i < 16; i++) {
                int kk = (i << 1) + ksub;
                ulonglong2 wp01 = *(const ulonglong2*)&Wsh[(kr + kk) * 32 + (cq << 3)];
                ulonglong2 wp23 = *(const ulonglong2*)&Wsh[(kr + kk) * 32 + (cq << 3) + 4];
                float4 h4 = *(const float4*)&hb[kk * 16 + (bq << 2)];
                u64t h0 = pack2(h4.x, h4.x);
                u64t h1 = pack2(h4.y, h4.y);
                u64t h2 = pack2(h4.z, h4.z);
                u64t h3 = pack2(h4.w, h4.w);
                acc[0][0] = fma2(wp01.x, h0, acc[0][0]);
                acc[0][1] = fma2(wp01.x, h1, acc[0][1]);
                acc[0][2] = fma2(wp01.x, h2, acc[0][2]);
                acc[0][3] = fma2(wp01.x, h3, acc[0][3]);
                acc[1][0] = fma2(wp01.y, h0, acc[1][0]);
                acc[1][1] = fma2(wp01.y, h1, acc[1][1]);
                acc[1][2] = fma2(wp01.y, h2, acc[1][2]);
                acc[1][3] = fma2(wp01.y, h3, acc[1][3]);
                acc[2][0] = fma2(wp23.x, h0, acc[2][0]);
                acc[2][1] = fma2(wp23.x, h1, acc[2][1]);
                acc[2][2] = fma2(wp23.x, h2, acc[2][2]);
                acc[2][3] = fma2(wp23.x, h3, acc[2][3]);
                acc[3][0] = fma2(wp23.y, h0, acc[3][0]);
                acc[3][1] = fma2(wp23.y, h1, acc[3][1]);
                acc[3][2] = fma2(wp23.y, h2, acc[3][2]);
                acc[3][3] = fma2(wp23.y, h3, acc[3][3]);
            }
        }

#pragma unroll
        for (int cp = 0; cp < 4; cp++)
#pragma unroll
            for (int j = 0; j < 4; j++)
                acc[cp][j] = add2(acc[cp][j],
                                  __shfl_xor_sync(0xFFFFFFFFu, acc[cp][j], 16));

        if (ksub == 0) {
            float* rw = red + w * 576;
#pragma unroll
            for (int j = 0; j < 4; j++) {
                int b_loc = (bq << 2) + j;
#pragma unroll
                for (int cph = 0; cph < 2; cph++) {
                    ulonglong2 v;
                    v.x = acc[2 * cph][j];
                    v.y = acc[2 * cph + 1][j];
                    *(ulonglong2*)&rw[b_loc * 36 + (cq << 3) + (cph << 2)] = v;
                }
            }
        }
        BARX(1);

        float sx = 0.0f, sy = 0.0f;
#pragma unroll
        for (int ww = 0; ww < 8; ww++) {
            sx += red[ww * 576 + b2 * 36 + c_l];
            sy += red[ww * 576 + (b2 + 1) * 36 + c_l];
        }
        float hv0 = tanhf(xp0 + sx);
        float hv1 = tanhf(xp1 + sy);
        __stcg((float2*)(hdst + c_g * Bb + B0 + b2), make_float2(hv0, hv1));

        BARX(1);
        if (t == 0 && step < Tt - 1) {
            arrive_release(cnt);
            unsigned target = 32u * (unsigned)(step + 1);
            while (ld_acquire(cnt) < target) { }
            int nb = (step + 1) >> 5;
            while (ld_acquire(&g_xcnt[nb]) < XP_TILES_PER_BLK) { }
        }
        __stcg(out + xi0, hv0);
        __stcg(out + xi1, hv1);
        if (step == Tt - 1) {
            out[Bb * Tt * Hh + (B0 + b2) * Hh + c_g] = hv0;
            out[Bb * Tt * Hh + (B0 + b2 + 1) * Hh + c_g] = hv1;
        }
        xi0 += Hh; xi1 += Hh;
        BARX(1);
    }
}

// ---------------------------------------------------------------------------
// Fused persistent kernel.
// ---------------------------------------------------------------------------
__global__ void __launch_bounds__(512, 1) regrnn_fused(
    const float* __restrict__ seq,
    const float* __restrict__ w_hh, const float* __restrict__ w_hh_mask,
    float* __restrict__ out)
{
    extern __shared__ __align__(16) float sm[];
    const int t = threadIdx.x;
    const int cta = blockIdx.x;
    const int half = t >> 8;
    const int rtid = t & 255;

    float* xpB_As = sm + RNN_FLOATS;
    float* xpB_Bs = xpB_As + 16 * 132;
    float* xpA_As = sm;
    float* xpA_Bs = xpA_As + 16 * 132;
    volatile unsigned* slot0 = (volatile unsigned*)(sm + RNN_FLOATS + XP_ROLE_FLOATS);
    volatile unsigned* slot1 = slot0 + 4;

    if (cta < FUSED_CTAS) {
        if (half == 0) {
            rnn_role(rtid, cta, w_hh, w_hh_mask, out, sm);
        } else {
            xproj_role(rtid, 2, xpB_As, xpB_Bs, slot1, seq, out);
        }
    } else {
        if (half == 0) {
            xproj_role(rtid, 1, xpA_As, xpA_Bs, slot0, seq, out);
        } else {
            xproj_role(rtid, 2, xpB_As, xpB_Bs, slot1, seq, out);
        }
    }

    // exit protocol: last CTA resets all counters for next graph replay
    if (t == 0) {
        __threadfence();
        unsigned old = atomicAdd(&g_done, 1u);
        if (old == TOTAL_CTAS - 1) {
#pragma unroll 8
            for (int i = 0; i < 128; i++) g_cnt[i] = 0u;
#pragma unroll
            for (int i = 0; i < XP_BLKS; i++) g_xcnt[i] = 0u;
            g_xtask = 0u;
            __threadfence();
            g_done = 0u;
        }
    }
}

// ---------------------------------------------------------------------------
extern "C" void kernel_launch(void* const* d_in, const int* in_sizes, int n_in,
                              void* d_out, int out_size) {
    (void)in_sizes; (void)n_in; (void)out_size;
    const float* seq       = (const float*)d_in[0];
    const float* w_ih      = (const float*)d_in[1];
    const float* w_ih_mask = (const float*)d_in[2];
    const float* w_hh      = (const float*)d_in[3];
    const float* w_hh_mask = (const float*)d_in[4];
    const float* b_ih      = (const float*)d_in[5];
    const float* b_ih_mask = (const float*)d_in[6];
    const float* b_hh      = (const float*)d_in[7];
    const float* b_hh_mask = (const float*)d_in[8];
    float* out = (float*)d_out;

    regrnn_prep<<<(Hh * Ii + 255) / 256, 256>>>(w_ih, w_ih_mask,
                                                b_ih, b_ih_mask, b_hh, b_hh_mask);

    cudaFuncSetAttribute(regrnn_fused, cudaFuncAttributeMaxDynamicSharedMemorySize, SMEM_BYTES);
    regrnn_fused<<<TOTAL_CTAS, 512, SMEM_BYTES>>>(seq, w_hh, w_hh_mask, out);
}

// round 15
// speedup vs baseline: 1.0184x; 1.0184x over previous
#include <cuda_runtime.h>
#include <cuda_bf16.h>
#include <cstdint>

#define Bb 64
#define Tt 512
#define Ii 1024
#define Hh 1024

#define FUSED_CTAS 128
#define TOTAL_CTAS 148
#define XP_UNITS 168          // 128 fused halves + 20*2 pure halves
#define XP_TILES 2048         // 16 blk * (16 bq * 8 nb)
#define XP_BLKS 16
#define XP_TILES_PER_BLK 128

// smem floats: rnn (Wsh 32768 + hs 16384 + red 8*576=4608) + xproj role-B (2*2112)
#define RNN_FLOATS (32768 + 16384 + 4608)
#define XP_ROLE_FLOATS (2 * 16 * 132)
#define SMEM_BYTES ((RNN_FLOATS + XP_ROLE_FLOATS) * 4)   // 231,936 B

__device__ __align__(16) float g_Wih[Hh * Ii];
__device__ __align__(16) float g_bias[Hh];
__device__ __align__(16) float g_hT[2 * Hh * Bb];   // double-buffered h, [k][b]
__device__ unsigned g_cnt[128];     // 4 h-barrier domains, stride 32
__device__ unsigned g_xcnt[XP_BLKS];// xproj per-t-block completion counters
__device__ unsigned g_done;

typedef unsigned long long u64t;

__device__ __forceinline__ u64t pack2(float x, float y) {
    u64t r; asm("mov.b64 %0, {%1,%2};" : "=l"(r) : "f"(x), "f"(y)); return r;
}
__device__ __forceinline__ u64t fma2(u64t a, u64t b, u64t c) {
    u64t d; asm("fma.rn.f32x2 %0, %1, %2, %3;" : "=l"(d) : "l"(a), "l"(b), "l"(c)); return d;
}
__device__ __forceinline__ u64t add2(u64t a, u64t b) {
    u64t d; asm("add.rn.f32x2 %0, %1, %2;" : "=l"(d) : "l"(a), "l"(b)); return d;
}
__device__ __forceinline__ float tanh_fast(float x) {
    float r; asm("tanh.approx.f32 %0, %1;" : "=f"(r) : "f"(x)); return r;
}
__device__ __forceinline__ void cpasync16(uint32_t dst, const void* src) {
    asm volatile("cp.async.cg.shared.global [%0], [%1], 16;" :: "r"(dst), "l"(src));
}
#define CP_COMMIT() asm volatile("cp.async.commit_group;")
#define BARX(id) asm volatile("bar.sync %0, %1;" :: "r"(id), "r"(256) : "memory")

__device__ __forceinline__ void arrive_release(unsigned* p) {
    asm volatile("red.release.gpu.global.add.u32 [%0], %1;" :: "l"(p), "r"(1u) : "memory");
}
__device__ __forceinline__ unsigned ld_acquire(unsigned* p) {
    unsigned v;
    asm volatile("ld.acquire.gpu.global.u32 %0, [%1];" : "=r"(v) : "l"(p) : "memory");
    return v;
}

__device__ __forceinline__ float hc_gate(float x) {
    float s = 1.0f / (1.0f + expf(-x));
    float v = s * 1.2f - 0.1f;
    return fminf(fmaxf(v, 0.0f), 1.0f);
}

// ---------------------------------------------------------------------------
// Phase 1: gate Wih + bias, zero h0, reset counters
// ---------------------------------------------------------------------------
__global__ void regrnn_prep(const float* __restrict__ w_ih, const float* __restrict__ w_ih_mask,
                            const float* __restrict__ b_ih, const float* __restrict__ b_ih_mask,
                            const float* __restrict__ b_hh, const float* __restrict__ b_hh_mask) {
    int i = blockIdx.x * blockDim.x + threadIdx.x;
    if (i < Hh * Ii) {
        g_Wih[i] = hc_gate(w_ih_mask[i]) * w_ih[i];
    }
    if (i < Hh) {
        g_bias[i] = hc_gate(b_ih_mask[i]) * b_ih[i] + hc_gate(b_hh_mask[i]) * b_hh[i];
    }
    if (i < 2 * Hh * Bb) g_hT[i] = 0.0f;
    if (i < 128) g_cnt[i] = 0u;
    if (i < XP_BLKS) g_xcnt[i] = 0u;
    if (i == 0) g_done = 0u;
}

// ---------------------------------------------------------------------------
// xproj role (R13 winner, static schedule): tiles unit, unit+168, ...
// Tile = (4 batches x 32 timesteps) x 128 n, t-block-major order.
// ---------------------------------------------------------------------------
__device__ void xproj_role(int rtid, int bid, float* As, float* Bs, int unit,
                           const float* __restrict__ A, float* __restrict__ out)
{
    const int wrole = rtid >> 5;
    const int lane = rtid & 31;
    const int ty = ((wrole & 1) << 3) + (lane >> 2);   // m-octet 0..15
    const int tx = ((wrole >> 1) << 2) + (lane & 3);   // n-octet 0..15

    const int i0 = rtid >> 2;
    const int k4 = (rtid & 3) << 2;
    const int i1 = i0 + 64;

    for (int tau = unit; tau < XP_TILES; tau += XP_UNITS) {
        const int blk = tau >> 7;
        const int r = tau & 127;
        const int b0 = (r >> 3) << 2;
        const int n0 = (r & 7) << 7;
        const int t0 = blk << 5;

        const int mrow0 = (b0 + (i0 >> 5)) * Tt + t0 + (i0 & 31);
        const int mrow1 = (b0 + (i1 >> 5)) * Tt + t0 + (i1 & 31);
        const float* pA0 = A + (size_t)mrow0 * Ii + k4;
        const float* pA1 = A + (size_t)mrow1 * Ii + k4;
        const float* pB0 = g_Wih + (size_t)(n0 + i0) * Ii + k4;
        const float* pB1 = g_Wih + (size_t)(n0 + i1) * Ii + k4;

        u64t acc[8][4];
#pragma unroll
        for (int i = 0; i < 8; i++)
#pragma unroll
            for (int j = 0; j < 4; j++) acc[i][j] = 0ULL;

        float4 a0v = *(const float4*)(pA0);
        float4 a1v = *(const float4*)(pA1);
        float4 b0v = *(const float4*)(pB0);
        float4 b1v = *(const float4*)(pB1);

        for (int kt = 0; kt < Ii; kt += 16) {
            As[(k4 + 0) * 132 + i0] = a0v.x; As[(k4 + 1) * 132 + i0] = a0v.y;
            As[(k4 + 2) * 132 + i0] = a0v.z; As[(k4 + 3) * 132 + i0] = a0v.w;
            As[(k4 + 0) * 132 + i1] = a1v.x; As[(k4 + 1) * 132 + i1] = a1v.y;
            As[(k4 + 2) * 132 + i1] = a1v.z; As[(k4 + 3) * 132 + i1] = a1v.w;
            Bs[(k4 + 0) * 132 + i0] = b0v.x; Bs[(k4 + 1) * 132 + i0] = b0v.y;
            Bs[(k4 + 2) * 132 + i0] = b0v.z; Bs[(k4 + 3) * 132 + i0] = b0v.w;
            Bs[(k4 + 0) * 132 + i1] = b1v.x; Bs[(k4 + 1) * 132 + i1] = b1v.y;
            Bs[(k4 + 2) * 132 + i1] = b1v.z; Bs[(k4 + 3) * 132 + i1] = b1v.w;
            BARX(bid);

            if (kt + 16 < Ii) {
                a0v = *(const float4*)(pA0 + kt + 16);
                a1v = *(const float4*)(pA1 + kt + 16);
                b0v = *(const float4*)(pB0 + kt + 16);
                b1v = *(const float4*)(pB1 + kt + 16);
            }

#pragma unroll
            for (int kk = 0; kk < 16; kk++) {
                float4 a0 = *(const float4*)&As[kk * 132 + (ty << 3)];
                float4 a1 = *(const float4*)&As[kk * 132 + (ty << 3) + 4];
                ulonglong2 b01 = *(const ulonglong2*)&Bs[kk * 132 + (tx << 3)];
                ulonglong2 b23 = *(const ulonglong2*)&Bs[kk * 132 + (tx << 3) + 4];
                float am[8] = {a0.x, a0.y, a0.z, a0.w, a1.x, a1.y, a1.z, a1.w};
#pragma unroll
                for (int mi = 0; mi < 8; mi++) {
                    u64t s = pack2(am[mi], am[mi]);
                    acc[mi][0] = fma2(s, b01.x, acc[mi][0]);
                    acc[mi][1] = fma2(s, b01.y, acc[mi][1]);
                    acc[mi][2] = fma2(s, b23.x, acc[mi][2]);
                    acc[mi][3] = fma2(s, b23.y, acc[mi][3]);
                }
            }
            BARX(bid);
        }

        const int n = n0 + (tx << 3);
        ulonglong2 bv0 = *(const ulonglong2*)(g_bias + n);
        ulonglong2 bv1 = *(const ulonglong2*)(g_bias + n + 4);
#pragma unroll
        for (int i = 0; i < 8; i++) {
            int mi = (ty << 3) + i;
            int mrow = (b0 + (mi >> 5)) * Tt + t0 + (mi & 31);
            ulonglong2 st0, st1;
            st0.x = add2(acc[i][0], bv0.x); st0.y = add2(acc[i][1], bv0.y);
            st1.x = add2(acc[i][2], bv1.x); st1.y = add2(acc[i][3], bv1.y);
            *(ulonglong2*)(out + (size_t)mrow * Hh + n) = st0;
            *(ulonglong2*)(out + (size_t)mrow * Hh + n + 4) = st1;
        }
        BARX(bid);
        if (rtid == 0) arrive_release(&g_xcnt[blk]);
    }
}

// ---------------------------------------------------------------------------
// rnn role: R13 compute core + float2 epilogue (c-pair per thread) +
// tanh.approx.f32.
// ---------------------------------------------------------------------------
__device__ void rnn_role(int t, int cta,
                         const float* __restrict__ w_hh, const float* __restrict__ w_hh_mask,
                         float* __restrict__ out, float* sm)
{
    float* Wsh = sm;                    // [1024][32]
    float* hsAll = sm + 32768;          // [8 warps][4 rounds][32 k][16 b]
    float* red = sm + 32768 + 16384;    // [8][16 b][36]

    const int w = t >> 5;
    const int lane = t & 31;
    const int cg = cta >> 2;
    const int bg = cta & 3;
    const int C0 = cg * 32;
    const int B0 = bg * 16;

    for (int i = t; i < 8192; i += 256) {
        int c = i & 31;
        int k4 = (i >> 5) << 2;
        size_t base = (size_t)(C0 + c) * Ii + k4;
        float4 wv = *(const float4*)(w_hh + base);
        float4 mv = *(const float4*)(w_hh_mask + base);
        Wsh[(k4 + 0) * 32 + c] = hc_gate(mv.x) * wv.x;
        Wsh[(k4 + 1) * 32 + c] = hc_gate(mv.y) * wv.y;
        Wsh[(k4 + 2) * 32 + c] = hc_gate(mv.z) * wv.z;
        Wsh[(k4 + 3) * 32 + c] = hc_gate(mv.w) * wv.w;
    }

    const int ksub = lane >> 4;
    const int tile = lane & 15;
    const int cq = tile >> 2;
    const int bq = tile & 3;

    float* hw = hsAll + w * 2048;
    uint32_t hw_u32 = (uint32_t)__cvta_generic_to_shared(hw);
    const int kbase = ((w + cg) & 7) * 128;

    // epilogue: thread owns (c2, c2+1) x b_l  -> float2 reduce/out/xp
    const int c2 = (t & 15) << 1;       // 0..30 even
    const int b_l = t >> 4;             // 0..15
    const int c_g = C0 + c2;

    unsigned* cnt = &g_cnt[bg * 32];

    int xi = ((B0 + b_l) * Tt) * Hh + c_g;

    if (t == 0) {
        while (ld_acquire(&g_xcnt[0]) < XP_TILES_PER_BLK) { }
    }
    BARX(1);

    for (int step = 0; step < Tt; step++) {
        const float* hsrc = g_hT + (step & 1) * (Hh * Bb);
        float* hdst = g_hT + ((step & 1) ^ 1) * (Hh * Bb);

#pragma unroll
        for (int r = 0; r < 4; r++) {
#pragma unroll
            for (int i = 0; i < 4; i++) {
                int fid = lane + (i << 5);
                int kk = fid >> 2;
                int c4 = (fid & 3) << 2;
                cpasync16(hw_u32 + ((r * 512 + kk * 16 + c4) << 2),
                          hsrc + (kbase + r * 32 + kk) * Bb + B0 + c4);
            }
            CP_COMMIT();
        }

        float2 xp = *(const float2*)(out + xi);   // x_proj pair (gated by xcnt)

        u64t acc[4][4];
#pragma unroll
        for (int i = 0; i < 4; i++)
#pragma unroll
            for (int j = 0; j < 4; j++) acc[i][j] = 0ULL;

#pragma unroll
        for (int r = 0; r < 4; r++) {
            switch (r) {
                case 0: asm volatile("cp.async.wait_group 3;"); break;
                case 1: asm volatile("cp.async.wait_group 2;"); break;
                case 2: asm volatile("cp.async.wait_group 1;"); break;
                default: asm volatile("cp.async.wait_group 0;"); break;
            }
            __syncwarp();
            const float* hb = hw + r * 512;
            const int kr = kbase + r * 32;
#pragma unroll
            for (int i = 0; i < 16; i++) {
                int kk = (i << 1) + ksub;
                ulonglong2 wp01 = *(const ulonglong2*)&Wsh[(kr + kk) * 32 + (cq << 3)];
                ulonglong2 wp23 = *(const ulonglong2*)&Wsh[(kr + kk) * 32 + (cq << 3) + 4];
                float4 h4 = *(const float4*)&hb[kk * 16 + (bq << 2)];
                u64t h0 = pack2(h4.x, h4.x);
                u64t h1 = pack2(h4.y, h4.y);
                u64t h2 = pack2(h4.z, h4.z);
                u64t h3 = pack2(h4.w, h4.w);
                acc[0][0] = fma2(wp01.x, h0, acc[0][0]);
                acc[0][1] = fma2(wp01.x, h1, acc[0][1]);
                acc[0][2] = fma2(wp01.x, h2, acc[0][2]);
                acc[0][3] = fma2(wp01.x, h3, acc[0][3]);
                acc[1][0] = fma2(wp01.y, h0, acc[1][0]);
                acc[1][1] = fma2(wp01.y, h1, acc[1][1]);
                acc[1][2] = fma2(wp01.y, h2, acc[1][2]);
                acc[1][3] = fma2(wp01.y, h3, acc[1][3]);
                acc[2][0] = fma2(wp23.x, h0, acc[2][0]);
                acc[2][1] = fma2(wp23.x, h1, acc[2][1]);
                acc[2][2] = fma2(wp23.x, h2, acc[2][2]);
                acc[2][3] = fma2(wp23.x, h3, acc[2][3]);
                acc[3][0] = fma2(wp23.y, h0, acc[3][0]);
                acc[3][1] = fma2(wp23.y, h1, acc[3][1]);
                acc[3][2] = fma2(wp23.y, h2, acc[3][2]);
                acc[3][3] = fma2(wp23.y, h3, acc[3][3]);
            }
        }

#pragma unroll
        for (int cp = 0; cp < 4; cp++)
#pragma unroll
            for (int j = 0; j < 4; j++)
                acc[cp][j] = add2(acc[cp][j],
                                  __shfl_xor_sync(0xFFFFFFFFu, acc[cp][j], 16));

        if (ksub == 0) {
            float* rw = red + w * 576;
#pragma unroll
            for (int j = 0; j < 4; j++) {
                int b_loc = (bq << 2) + j;
#pragma unroll
                for (int cph = 0; cph < 2; cph++) {
                    ulonglong2 v;
                    v.x = acc[2 * cph][j];
                    v.y = acc[2 * cph + 1][j];
                    *(ulonglong2*)&rw[b_loc * 36 + (cq << 3) + (cph << 2)] = v;
                }
            }
        }
        BARX(1);

        // reduce 8 partials with float2 loads (adjacent c), tanh.approx
        float sx = 0.0f, sy = 0.0f;
#pragma unroll
        for (int ww = 0; ww < 8; ww++) {
            float2 v = *(const float2*)&red[ww * 576 + b_l * 36 + c2];
            sx += v.x; sy += v.y;
        }
        float hv0 = tanh_fast(xp.x + sx);
        float hv1 = tanh_fast(xp.y + sy);
        __stcg(hdst + c_g * Bb + B0 + b_l, hv0);
        __stcg(hdst + (c_g + 1) * Bb + B0 + b_l, hv1);

        BARX(1);
        if (t == 0 && step < Tt - 1) {
            arrive_release(cnt);
            unsigned target = 32u * (unsigned)(step + 1);
            while (ld_acquire(cnt) < target) { }
            int nb = (step + 1) >> 5;
            while (ld_acquire(&g_xcnt[nb]) < XP_TILES_PER_BLK) { }
        }
        // out writes overlap t0's spin
        __stcg((float2*)(out + xi), make_float2(hv0, hv1));
        if (step == Tt - 1) {
            *(float2*)(out + Bb * Tt * Hh + (B0 + b_l) * Hh + c_g) = make_float2(hv0, hv1);
        }
        xi += Hh;
        BARX(1);
    }
}

// ---------------------------------------------------------------------------
// Fused persistent kernel (R13 structure).
// ---------------------------------------------------------------------------
__global__ void __launch_bounds__(512, 1) regrnn_fused(
    const float* __restrict__ seq,
    const float* __restrict__ w_hh, const float* __restrict__ w_hh_mask,
    float* __restrict__ out)
{
    extern __shared__ __align__(16) float sm[];
    const int t = threadIdx.x;
    const int cta = blockIdx.x;
    const int half = t >> 8;
    const int rtid = t & 255;

    float* xpB_As = sm + RNN_FLOATS;
    float* xpB_Bs = xpB_As + 16 * 132;
    float* xpA_As = sm;
    float* xpA_Bs = xpA_As + 16 * 132;

    if (cta < FUSED_CTAS) {
        if (half == 0) {
            rnn_role(rtid, cta, w_hh, w_hh_mask, out, sm);
        } else {
            xproj_role(rtid, 2, xpB_As, xpB_Bs, cta, seq, out);
        }
    } else {
        if (half == 0) {
            xproj_role(rtid, 1, xpA_As, xpA_Bs, FUSED_CTAS + (cta - FUSED_CTAS) * 2, seq, out);
        } else {
            xproj_role(rtid, 2, xpB_As, xpB_Bs, FUSED_CTAS + (cta - FUSED_CTAS) * 2 + 1, seq, out);
        }
    }

    // exit protocol: last CTA resets all counters for next graph replay
    if (t == 0) {
        __threadfence();
        unsigned old = atomicAdd(&g_done, 1u);
        if (old == TOTAL_CTAS - 1) {
#pragma unroll 8
            for (int i = 0; i < 128; i++) g_cnt[i] = 0u;
#pragma unroll
            for (int i = 0; i < XP_BLKS; i++) g_xcnt[i] = 0u;
            __threadfence();
            g_done = 0u;
        }
    }
}

// ---------------------------------------------------------------------------
extern "C" void kernel_launch(void* const* d_in, const int* in_sizes, int n_in,
                              void* d_out, int out_size) {
    (void)in_sizes; (void)n_in; (void)out_size;
    const float* seq       = (const float*)d_in[0];
    const float* w_ih      = (const float*)d_in[1];
    const float* w_ih_mask = (const float*)d_in[2];
    const float* w_hh      = (const float*)d_in[3];
    const float* w_hh_mask = (const float*)d_in[4];
    const float* b_ih      = (const float*)d_in[5];
    const float* b_ih_mask = (const float*)d_in[6];
    const float* b_hh      = (const float*)d_in[7];
    const float* b_hh_mask = (const float*)d_in[8];
    float* out = (float*)d_out;

    regrnn_prep<<<(Hh * Ii + 255) / 256, 256>>>(w_ih, w_ih_mask,
                                                b_ih, b_ih_mask, b_hh, b_hh_mask);

    cudaFuncSetAttribute(regrnn_fused, cudaFuncAttributeMaxDynamicSharedMemorySize, SMEM_BYTES);
    regrnn_fused<<<TOTAL_CTAS, 512, SMEM_BYTES>>>(seq, w_hh, w_hh_mask, out);
}

// round 16
// speedup vs baseline: 1.0304x; 1.0118x over previous
#include <cuda_runtime.h>
#include <cuda_bf16.h>
#include <cstdint>

#define Bb 64
#define Tt 512
#define Ii 1024
#define Hh 1024

#define FUSED_CTAS 128
#define TOTAL_CTAS 148
#define XP_UNITS 168          // 128 fused halves + 20*2 pure halves
#define XP_TILES 4096         // 16 blk * (32 bpair * 8 nb)
#define XP_BLKS 16
#define XP_TILES_PER_BLK 256

// rnn smem floats: Wsh 32768 + hs 16384 + red 8*576=4608
#define RNN_FLOATS (32768 + 16384 + 4608)
// xproj role: Ah/Al [64][24] bf16 + Bh/Bl [128][16] bf16 = 14336 B
#define XP_ROLE_BYTES 14336
#define SMEM_BYTES (RNN_FLOATS * 4 + XP_ROLE_BYTES)   // 229,376 B

__device__ __align__(16) __nv_bfloat16 g_wih_hi[Hh * Ii];
__device__ __align__(16) __nv_bfloat16 g_wih_lo[Hh * Ii];
__device__ __align__(16) float g_bias[Hh];
__device__ __align__(16) float g_hT[2 * Hh * Bb];   // double-buffered h, [k][b]
__device__ unsigned g_cnt[128];     // 4 h-barrier domains, stride 32
__device__ unsigned g_xcnt[XP_BLKS];
__device__ unsigned g_done;

typedef unsigned long long u64t;

__device__ __forceinline__ u64t pack2(float x, float y) {
    u64t r; asm("mov.b64 %0, {%1,%2};" : "=l"(r) : "f"(x), "f"(y)); return r;
}
__device__ __forceinline__ u64t fma2(u64t a, u64t b, u64t c) {
    u64t d; asm("fma.rn.f32x2 %0, %1, %2, %3;" : "=l"(d) : "l"(a), "l"(b), "l"(c)); return d;
}
__device__ __forceinline__ u64t add2(u64t a, u64t b) {
    u64t d; asm("add.rn.f32x2 %0, %1, %2;" : "=l"(d) : "l"(a), "l"(b)); return d;
}
__device__ __forceinline__ float tanh_fast(float x) {
    float r; asm("tanh.approx.f32 %0, %1;" : "=f"(r) : "f"(x)); return r;
}
__device__ __forceinline__ void cpasync16(uint32_t dst, const void* src) {
    asm volatile("cp.async.cg.shared.global [%0], [%1], 16;" :: "r"(dst), "l"(src));
}
#define CP_COMMIT() asm volatile("cp.async.commit_group;")
#define BARX(id) asm volatile("bar.sync %0, %1;" :: "r"(id), "r"(256) : "memory")

__device__ __forceinline__ void arrive_release(unsigned* p) {
    asm volatile("red.release.gpu.global.add.u32 [%0], %1;" :: "l"(p), "r"(1u) : "memory");
}
__device__ __forceinline__ unsigned ld_acquire(unsigned* p) {
    unsigned v;
    asm volatile("ld.acquire.gpu.global.u32 %0, [%1];" : "=r"(v) : "l"(p) : "memory");
    return v;
}

__device__ __forceinline__ void ldsm_x4(uint32_t* r, uint32_t addr) {
    asm volatile("ldmatrix.sync.aligned.m8n8.x4.shared.b16 {%0,%1,%2,%3}, [%4];"
        : "=r"(r[0]), "=r"(r[1]), "=r"(r[2]), "=r"(r[3]) : "r"(addr));
}
__device__ __forceinline__ void ldsm_x2(uint32_t* r, uint32_t addr) {
    asm volatile("ldmatrix.sync.aligned.m8n8.x2.shared.b16 {%0,%1}, [%2];"
        : "=r"(r[0]), "=r"(r[1]) : "r"(addr));
}
__device__ __forceinline__ void mma_bf16(float* d, const uint32_t* a, const uint32_t* b) {
    asm volatile("mma.sync.aligned.m16n8k16.row.col.f32.bf16.bf16.f32 "
        "{%0,%1,%2,%3}, {%4,%5,%6,%7}, {%8,%9}, {%0,%1,%2,%3};"
        : "+f"(d[0]), "+f"(d[1]), "+f"(d[2]), "+f"(d[3])
        : "r"(a[0]), "r"(a[1]), "r"(a[2]), "r"(a[3]), "r"(b[0]), "r"(b[1]));
}

// split 8 consecutive floats into hi/lo bf16 (memory order preserved)
__device__ __forceinline__ void split8(float4 u, float4 v, uint4& hi, uint4& lo) {
    float f[8] = {u.x, u.y, u.z, u.w, v.x, v.y, v.z, v.w};
    unsigned hw[4], lw[4];
#pragma unroll
    for (int q = 0; q < 4; q++) {
        float a = f[2 * q], b = f[2 * q + 1];
        __nv_bfloat16 ha = __float2bfloat16(a), hb = __float2bfloat16(b);
        float ra = a - __bfloat162float(ha), rb = b - __bfloat162float(hb);
        __nv_bfloat162 hp(ha, hb);
        __nv_bfloat162 lp(__float2bfloat16(ra), __float2bfloat16(rb));
        hw[q] = *(unsigned*)&hp;
        lw[q] = *(unsigned*)&lp;
    }
    hi = make_uint4(hw[0], hw[1], hw[2], hw[3]);
    lo = make_uint4(lw[0], lw[1], lw[2], lw[3]);
}

__device__ __forceinline__ float hc_gate(float x) {
    float s = 1.0f / (1.0f + expf(-x));
    float v = s * 1.2f - 0.1f;
    return fminf(fmaxf(v, 0.0f), 1.0f);
}

// ---------------------------------------------------------------------------
// Phase 1: gate + bf16-split Wih, bias, zero h0, reset counters
// ---------------------------------------------------------------------------
__global__ void regrnn_prep(const float* __restrict__ w_ih, const float* __restrict__ w_ih_mask,
                            const float* __restrict__ b_ih, const float* __restrict__ b_ih_mask,
                            const float* __restrict__ b_hh, const float* __restrict__ b_hh_mask) {
    int i = blockIdx.x * blockDim.x + threadIdx.x;
    if (i < Hh * Ii) {
        float g = hc_gate(w_ih_mask[i]) * w_ih[i];
        __nv_bfloat16 h = __float2bfloat16(g);
        g_wih_hi[i] = h;
        g_wih_lo[i] = __float2bfloat16(g - __bfloat162float(h));
    }
    if (i < Hh) {
        g_bias[i] = hc_gate(b_ih_mask[i]) * b_ih[i] + hc_gate(b_hh_mask[i]) * b_hh[i];
    }
    if (i < 2 * Hh * Bb) g_hT[i] = 0.0f;
    if (i < 128) g_cnt[i] = 0u;
    if (i < XP_BLKS) g_xcnt[i] = 0u;
    if (i == 0) g_done = 0u;
}

// ---------------------------------------------------------------------------
// xproj role on TENSOR pipe: 64m x 128n tile, bf16 3-term split mma.
// D = Ah*Bh + Ah*Bl + Al*Bh (fp32 acc). A (seq) split on the fly.
// Warp w owns n columns [w*16, w*16+16); 4 m16-tiles; k chunks of 16.
// ---------------------------------------------------------------------------
__device__ void xproj_role(int rtid, int bid, char* xsm, int unit,
                           const float* __restrict__ seq, float* __restrict__ out)
{
    __nv_bfloat16* Ah = (__nv_bfloat16*)xsm;            // [64][24]
    __nv_bfloat16* Al = Ah + 64 * 24;
    __nv_bfloat16* Bh = Al + 64 * 24;                   // [128][16]
    __nv_bfloat16* Bl = Bh + 128 * 16;
    const uint32_t Ah_u = (uint32_t)__cvta_generic_to_shared(Ah);
    const uint32_t Al_u = (uint32_t)__cvta_generic_to_shared(Al);
    const uint32_t Bh_u = (uint32_t)__cvta_generic_to_shared(Bh);
    const uint32_t Bl_u = (uint32_t)__cvta_generic_to_shared(Bl);

    const int w = rtid >> 5;
    const int lane = rtid & 31;
    const int gid = lane >> 2;
    const int tig = lane & 3;

    const uint32_t inv_a = (uint32_t)((((lane & 7) + ((lane >> 3) & 1) * 8) * 48) + ((lane >> 4) * 16));
    const uint32_t inv_b = (uint32_t)(((lane & 7) * 32) + (((lane >> 3) & 1) * 16));

    const int am = rtid >> 1;        // valid for rtid < 128: m row 0..63
    const int ahalf = rtid & 1;
    const int bn = rtid >> 1;        // n row 0..127
    const int bhalf = rtid & 1;

    for (int tau = unit; tau < XP_TILES; tau += XP_UNITS) {
        const int blk = tau >> 8;
        const int r = tau & 255;
        const int b0 = (r >> 3) << 1;       // 2-batch group
        const int n0 = (r & 7) << 7;        // n-tile base
        const int t0 = blk << 5;            // 32-t block

        const float* aptr = seq;            // set properly below for rtid<128
        if (rtid < 128) {
            int mrow = (b0 + (am >> 5)) * Tt + t0 + (am & 31);
            aptr = seq + (size_t)mrow * Ii + ahalf * 8;
        }
        const __nv_bfloat16* bhp = g_wih_hi + (size_t)(n0 + bn) * Ii + bhalf * 8;
        const __nv_bfloat16* blp = g_wih_lo + (size_t)(n0 + bn) * Ii + bhalf * 8;

        float acc[4][2][4];
#pragma unroll
        for (int i = 0; i < 4; i++)
#pragma unroll
            for (int j = 0; j < 2; j++)
#pragma unroll
                for (int q = 0; q < 4; q++) acc[i][j][q] = 0.0f;

        // prefetch chunk 0
        float4 av0, av1;
        if (rtid < 128) { av0 = *(const float4*)(aptr); av1 = *(const float4*)(aptr + 4); }
        uint4 bhv = *(const uint4*)(bhp);
        uint4 blv = *(const uint4*)(blp);

        for (int kt = 0; kt < Ii; kt += 16) {
            // stage current chunk
            if (rtid < 128) {
                uint4 hi4, lo4;
                split8(av0, av1, hi4, lo4);
                *(uint4*)(Ah + am * 24 + ahalf * 8) = hi4;
                *(uint4*)(Al + am * 24 + ahalf * 8) = lo4;
            }
            *(uint4*)(Bh + bn * 16 + bhalf * 8) = bhv;
            *(uint4*)(Bl + bn * 16 + bhalf * 8) = blv;
            BARX(bid);

            // prefetch next chunk
            if (kt + 16 < Ii) {
                if (rtid < 128) {
                    av0 = *(const float4*)(aptr + kt + 16);
                    av1 = *(const float4*)(aptr + kt + 20);
                }
                bhv = *(const uint4*)(bhp + kt + 16);
                blv = *(const uint4*)(blp + kt + 16);
            }

            // compute: B fragments per warp (2 n8-tiles x hi/lo)
            uint32_t bhf[2][2], blf[2][2];
#pragma unroll
            for (int nt = 0; nt < 2; nt++) {
                uint32_t boff = (uint32_t)((w * 16 + nt * 8) * 32) + inv_b;
                ldsm_x2(bhf[nt], Bh_u + boff);
                ldsm_x2(blf[nt], Bl_u + boff);
            }
#pragma unroll
            for (int mt = 0; mt < 4; mt++) {
                uint32_t ahf[4], alf[4];
                ldsm_x4(ahf, Ah_u + (uint32_t)(mt * 768) + inv_a);
                ldsm_x4(alf, Al_u + (uint32_t)(mt * 768) + inv_a);
#pragma unroll
                for (int nt = 0; nt < 2; nt++) {
                    mma_bf16(acc[mt][nt], ahf, bhf[nt]);
                    mma_bf16(acc[mt][nt], ahf, blf[nt]);
                    mma_bf16(acc[mt][nt], alf, bhf[nt]);
                }
            }
            BARX(bid);
        }

        // epilogue: D fragment rows m = mt*16 + gid (+8), cols 2*tig (+1)
#pragma unroll
        for (int nt = 0; nt < 2; nt++) {
            int col = n0 + w * 16 + nt * 8 + 2 * tig;
            float2 bv = *(const float2*)&g_bias[col];
#pragma unroll
            for (int mt = 0; mt < 4; mt++) {
                int m0r = mt * 16 + gid;
                int mrow0 = (b0 + (m0r >> 5)) * Tt + t0 + (m0r & 31);
                float2 o0;
                o0.x = acc[mt][nt][0] + bv.x;
                o0.y = acc[mt][nt][1] + bv.y;
                *(float2*)(out + (size_t)mrow0 * Hh + col) = o0;
                int m1r = m0r + 8;
                int mrow1 = (b0 + (m1r >> 5)) * Tt + t0 + (m1r & 31);
                float2 o1;
                o1.x = acc[mt][nt][2] + bv.x;
                o1.y = acc[mt][nt][3] + bv.y;
                *(float2*)(out + (size_t)mrow1 * Hh + col) = o1;
            }
        }
        BARX(bid);   // all stores done before counting
        if (rtid == 0) arrive_release(&g_xcnt[blk]);
    }
}

// ---------------------------------------------------------------------------
// rnn role: R15 winner, unchanged (gating constant updated to 256).
// ---------------------------------------------------------------------------
__device__ void rnn_role(int t, int cta,
                         const float* __restrict__ w_hh, const float* __restrict__ w_hh_mask,
                         float* __restrict__ out, float* sm)
{
    float* Wsh = sm;                    // [1024][32]
    float* hsAll = sm + 32768;          // [8 warps][4 rounds][32 k][16 b]
    float* red = sm + 32768 + 16384;    // [8][16 b][36]

    const int w = t >> 5;
    const int lane = t & 31;
    const int cg = cta >> 2;
    const int bg = cta & 3;
    const int C0 = cg * 32;
    const int B0 = bg * 16;

    for (int i = t; i < 8192; i += 256) {
        int c = i & 31;
        int k4 = (i >> 5) << 2;
        size_t base = (size_t)(C0 + c) * Ii + k4;
        float4 wv = *(const float4*)(w_hh + base);
        float4 mv = *(const float4*)(w_hh_mask + base);
        Wsh[(k4 + 0) * 32 + c] = hc_gate(mv.x) * wv.x;
        Wsh[(k4 + 1) * 32 + c] = hc_gate(mv.y) * wv.y;
        Wsh[(k4 + 2) * 32 + c] = hc_gate(mv.z) * wv.z;
        Wsh[(k4 + 3) * 32 + c] = hc_gate(mv.w) * wv.w;
    }

    const int ksub = lane >> 4;
    const int tile = lane & 15;
    const int cq = tile >> 2;
    const int bq = tile & 3;

    float* hw = hsAll + w * 2048;
    uint32_t hw_u32 = (uint32_t)__cvta_generic_to_shared(hw);
    const int kbase = ((w + cg) & 7) * 128;

    const int c2 = (t & 15) << 1;
    const int b_l = t >> 4;
    const int c_g = C0 + c2;

    unsigned* cnt = &g_cnt[bg * 32];

    int xi = ((B0 + b_l) * Tt) * Hh + c_g;

    if (t == 0) {
        while (ld_acquire(&g_xcnt[0]) < XP_TILES_PER_BLK) { }
    }
    BARX(1);

    for (int step = 0; step < Tt; step++) {
        const float* hsrc = g_hT + (step & 1) * (Hh * Bb);
        float* hdst = g_hT + ((step & 1) ^ 1) * (Hh * Bb);

#pragma unroll
        for (int r = 0; r < 4; r++) {
#pragma unroll
            for (int i = 0; i < 4; i++) {
                int fid = lane + (i << 5);
                int kk = fid >> 2;
                int c4 = (fid & 3) << 2;
                cpasync16(hw_u32 + ((r * 512 + kk * 16 + c4) << 2),
                          hsrc + (kbase + r * 32 + kk) * Bb + B0 + c4);
            }
            CP_COMMIT();
        }

        float2 xp = *(const float2*)(out + xi);

        u64t acc[4][4];
#pragma unroll
        for (int i = 0; i < 4; i++)
#pragma unroll
            for (int j = 0; j < 4; j++) acc[i][j] = 0ULL;

#pragma unroll
        for (int r = 0; r < 4; r++) {
            switch (r) {
                case 0: asm volatile("cp.async.wait_group 3;"); break;
                case 1: asm volatile("cp.async.wait_group 2;"); break;
                case 2: asm volatile("cp.async.wait_group 1;"); break;
                default: asm volatile("cp.async.wait_group 0;"); break;
            }
            __syncwarp();
            const float* hb = hw + r * 512;
            const int kr = kbase + r * 32;
#pragma unroll
            for (int i = 0; i < 16; i++) {
                int kk = (i << 1) + ksub;
                ulonglong2 wp01 = *(const ulonglong2*)&Wsh[(kr + kk) * 32 + (cq << 3)];
                ulonglong2 wp23 = *(const ulonglong2*)&Wsh[(kr + kk) * 32 + (cq << 3) + 4];
                float4 h4 = *(const float4*)&hb[kk * 16 + (bq << 2)];
                u64t h0 = pack2(h4.x, h4.x);
                u64t h1 = pack2(h4.y, h4.y);
                u64t h2 = pack2(h4.z, h4.z);
                u64t h3 = pack2(h4.w, h4.w);
                acc[0][0] = fma2(wp01.x, h0, acc[0][0]);
                acc[0][1] = fma2(wp01.x, h1, acc[0][1]);
                acc[0][2] = fma2(wp01.x, h2, acc[0][2]);
                acc[0][3] = fma2(wp01.x, h3, acc[0][3]);
                acc[1][0] = fma2(wp01.y, h0, acc[1][0]);
                acc[1][1] = fma2(wp01.y, h1, acc[1][1]);
                acc[1][2] = fma2(wp01.y, h2, acc[1][2]);
                acc[1][3] = fma2(wp01.y, h3, acc[1][3]);
                acc[2][0] = fma2(wp23.x, h0, acc[2][0]);
                acc[2][1] = fma2(wp23.x, h1, acc[2][1]);
                acc[2][2] = fma2(wp23.x, h2, acc[2][2]);
                acc[2][3] = fma2(wp23.x, h3, acc[2][3]);
                acc[3][0] = fma2(wp23.y, h0, acc[3][0]);
                acc[3][1] = fma2(wp23.y, h1, acc[3][1]);
                acc[3][2] = fma2(wp23.y, h2, acc[3][2]);
                acc[3][3] = fma2(wp23.y, h3, acc[3][3]);
            }
        }

#pragma unroll
        for (int cp = 0; cp < 4; cp++)
#pragma unroll
            for (int j = 0; j < 4; j++)
                acc[cp][j] = add2(acc[cp][j],
                                  __shfl_xor_sync(0xFFFFFFFFu, acc[cp][j], 16));

        if (ksub == 0) {
            float* rw = red + w * 576;
#pragma unroll
            for (int j = 0; j < 4; j++) {
                int b_loc = (bq << 2) + j;
#pragma unroll
                for (int cph = 0; cph < 2; cph++) {
                    ulonglong2 v;
                    v.x = acc[2 * cph][j];
                    v.y = acc[2 * cph + 1][j];
                    *(ulonglong2*)&rw[b_loc * 36 + (cq << 3) + (cph << 2)] = v;
                }
            }
        }
        BARX(1);

        float sx = 0.0f, sy = 0.0f;
#pragma unroll
        for (int ww = 0; ww < 8; ww++) {
            float2 v = *(const float2*)&red[ww * 576 + b_l * 36 + c2];
            sx += v.x; sy += v.y;
        }
        float hv0 = tanh_fast(xp.x + sx);
        float hv1 = tanh_fast(xp.y + sy);
        __stcg(hdst + c_g * Bb + B0 + b_l, hv0);
        __stcg(hdst + (c_g + 1) * Bb + B0 + b_l, hv1);

        BARX(1);
        if (t == 0 && step < Tt - 1) {
            arrive_release(cnt);
            unsigned target = 32u * (unsigned)(step + 1);
            while (ld_acquire(cnt) < target) { }
            int nb = (step + 1) >> 5;
            while (ld_acquire(&g_xcnt[nb]) < XP_TILES_PER_BLK) { }
        }
        __stcg((float2*)(out + xi), make_float2(hv0, hv1));
        if (step == Tt - 1) {
            *(float2*)(out + Bb * Tt * Hh + (B0 + b_l) * Hh + c_g) = make_float2(hv0, hv1);
        }
        xi += Hh;
        BARX(1);
    }
}

// ---------------------------------------------------------------------------
// Fused persistent kernel.
// ---------------------------------------------------------------------------
__global__ void __launch_bounds__(512, 1) regrnn_fused(
    const float* __restrict__ seq,
    const float* __restrict__ w_hh, const float* __restrict__ w_hh_mask,
    float* __restrict__ out)
{
    extern __shared__ __align__(16) float sm[];
    const int t = threadIdx.x;
    const int cta = blockIdx.x;
    const int half = t >> 8;
    const int rtid = t & 255;

    char* xsmB = (char*)(sm + RNN_FLOATS);   // role-B xproj region
    char* xsmA = (char*)sm;                  // role-A (pure CTAs reuse rnn area)

    if (cta < FUSED_CTAS) {
        if (half == 0) {
            rnn_role(rtid, cta, w_hh, w_hh_mask, out, sm);
        } else {
            xproj_role(rtid, 2, xsmB, cta, seq, out);
        }
    } else {
        if (half == 0) {
            xproj_role(rtid, 1, xsmA, FUSED_CTAS + (cta - FUSED_CTAS) * 2, seq, out);
        } else {
            xproj_role(rtid, 2, xsmB, FUSED_CTAS + (cta - FUSED_CTAS) * 2 + 1, seq, out);
        }
    }

    // exit protocol: last CTA resets all counters for next graph replay
    if (t == 0) {
        __threadfence();
        unsigned old = atomicAdd(&g_done, 1u);
        if (old == TOTAL_CTAS - 1) {
#pragma unroll 8
            for (int i = 0; i < 128; i++) g_cnt[i] = 0u;
#pragma unroll
            for (int i = 0; i < XP_BLKS; i++) g_xcnt[i] = 0u;
            __threadfence();
            g_done = 0u;
        }
    }
}

// ---------------------------------------------------------------------------
extern "C" void kernel_launch(void* const* d_in, const int* in_sizes, int n_in,
                              void* d_out, int out_size) {
    (void)in_sizes; (void)n_in; (void)out_size;
    const float* seq       = (const float*)d_in[0];
    const float* w_ih      = (const float*)d_in[1];
    const float* w_ih_mask = (const float*)d_in[2];
    const float* w_hh      = (const float*)d_in[3];
    const float* w_hh_mask = (const float*)d_in[4];
    const float* b_ih      = (const float*)d_in[5];
    const float* b_ih_mask = (const float*)d_in[6];
    const float* b_hh      = (const float*)d_in[7];
    const float* b_hh_mask = (const float*)d_in[8];
    float* out = (float*)d_out;

    regrnn_prep<<<(Hh * Ii + 255) / 256, 256>>>(w_ih, w_ih_mask,
                                                b_ih, b_ih_mask, b_hh, b_hh_mask);

    cudaFuncSetAttribute(regrnn_fused, cudaFuncAttributeMaxDynamicSharedMemorySize, SMEM_BYTES);
    regrnn_fused<<<TOTAL_CTAS, 512, SMEM_BYTES>>>(seq, w_hh, w_hh_mask, out);
}

// round 17
// speedup vs baseline: 1.0649x; 1.0335x over previous
#include <cuda_runtime.h>
#include <cuda_bf16.h>
#include <cstdint>

#define Bb 64
#define Tt 512
#define Ii 1024
#define Hh 1024

#define FUSED_CTAS 128
#define TOTAL_CTAS 148
#define XP_UNITS 168          // 128 fused halves + 20*2 pure halves
#define XP_TILES 4096         // 16 blk * (32 bpair * 8 nb)
#define XP_BLKS 16
#define XP_TILES_PER_BLK 256

// rnn smem floats: Wsh 32768 + hs 16384 + red 8*576=4608
#define RNN_FLOATS (32768 + 16384 + 4608)
// xproj role: Ah/Al [64][24] bf16 + Bh/Bl [128][16] bf16 = 14336 B
#define XP_ROLE_BYTES 14336
#define SMEM_BYTES (RNN_FLOATS * 4 + XP_ROLE_BYTES)   // 229,376 B

__device__ __align__(16) __nv_bfloat16 g_wih_hi[Hh * Ii];
__device__ __align__(16) __nv_bfloat16 g_wih_lo[Hh * Ii];
__device__ __align__(16) float g_bias[Hh];
__device__ __align__(16) float g_hT[2 * Hh * Bb];   // double-buffered h, [k][b]
__device__ unsigned g_cnt[128];     // 4 h-barrier domains, stride 32
__device__ unsigned g_xcnt[XP_BLKS];
__device__ unsigned g_done;

typedef unsigned long long u64t;

__device__ __forceinline__ u64t pack2(float x, float y) {
    u64t r; asm("mov.b64 %0, {%1,%2};" : "=l"(r) : "f"(x), "f"(y)); return r;
}
__device__ __forceinline__ u64t fma2(u64t a, u64t b, u64t c) {
    u64t d; asm("fma.rn.f32x2 %0, %1, %2, %3;" : "=l"(d) : "l"(a), "l"(b), "l"(c)); return d;
}
__device__ __forceinline__ u64t add2(u64t a, u64t b) {
    u64t d; asm("add.rn.f32x2 %0, %1, %2;" : "=l"(d) : "l"(a), "l"(b)); return d;
}
__device__ __forceinline__ float tanh_fast(float x) {
    float r; asm("tanh.approx.f32 %0, %1;" : "=f"(r) : "f"(x)); return r;
}
__device__ __forceinline__ void cpasync16(uint32_t dst, const void* src) {
    asm volatile("cp.async.cg.shared.global [%0], [%1], 16;" :: "r"(dst), "l"(src));
}
#define CP_COMMIT() asm volatile("cp.async.commit_group;")
#define BARX(id) asm volatile("bar.sync %0, %1;" :: "r"(id), "r"(256) : "memory")

__device__ __forceinline__ void arrive_release(unsigned* p) {
    asm volatile("red.release.gpu.global.add.u32 [%0], %1;" :: "l"(p), "r"(1u) : "memory");
}
__device__ __forceinline__ unsigned ld_acquire(unsigned* p) {
    unsigned v;
    asm volatile("ld.acquire.gpu.global.u32 %0, [%1];" : "=r"(v) : "l"(p) : "memory");
    return v;
}

__device__ __forceinline__ void ldsm_x4(uint32_t* r, uint32_t addr) {
    asm volatile("ldmatrix.sync.aligned.m8n8.x4.shared.b16 {%0,%1,%2,%3}, [%4];"
        : "=r"(r[0]), "=r"(r[1]), "=r"(r[2]), "=r"(r[3]) : "r"(addr));
}
__device__ __forceinline__ void ldsm_x2(uint32_t* r, uint32_t addr) {
    asm volatile("ldmatrix.sync.aligned.m8n8.x2.shared.b16 {%0,%1}, [%2];"
        : "=r"(r[0]), "=r"(r[1]) : "r"(addr));
}
__device__ __forceinline__ void mma_bf16(float* d, const uint32_t* a, const uint32_t* b) {
    asm volatile("mma.sync.aligned.m16n8k16.row.col.f32.bf16.bf16.f32 "
        "{%0,%1,%2,%3}, {%4,%5,%6,%7}, {%8,%9}, {%0,%1,%2,%3};"
        : "+f"(d[0]), "+f"(d[1]), "+f"(d[2]), "+f"(d[3])
        : "r"(a[0]), "r"(a[1]), "r"(a[2]), "r"(a[3]), "r"(b[0]), "r"(b[1]));
}

// split 8 consecutive floats into hi/lo bf16 (memory order preserved)
__device__ __forceinline__ void split8(float4 u, float4 v, uint4& hi, uint4& lo) {
    float f[8] = {u.x, u.y, u.z, u.w, v.x, v.y, v.z, v.w};
    unsigned hw[4], lw[4];
#pragma unroll
    for (int q = 0; q < 4; q++) {
        float a = f[2 * q], b = f[2 * q + 1];
        __nv_bfloat16 ha = __float2bfloat16(a), hb = __float2bfloat16(b);
        float ra = a - __bfloat162float(ha), rb = b - __bfloat162float(hb);
        __nv_bfloat162 hp(ha, hb);
        __nv_bfloat162 lp(__float2bfloat16(ra), __float2bfloat16(rb));
        hw[q] = *(unsigned*)&hp;
        lw[q] = *(unsigned*)&lp;
    }
    hi = make_uint4(hw[0], hw[1], hw[2], hw[3]);
    lo = make_uint4(lw[0], lw[1], lw[2], lw[3]);
}

__device__ __forceinline__ float hc_gate(float x) {
    float s = 1.0f / (1.0f + expf(-x));
    float v = s * 1.2f - 0.1f;
    return fminf(fmaxf(v, 0.0f), 1.0f);
}

// ---------------------------------------------------------------------------
// Phase 1: gate + bf16-split Wih, bias, zero h0, reset counters
// ---------------------------------------------------------------------------
__global__ void regrnn_prep(const float* __restrict__ w_ih, const float* __restrict__ w_ih_mask,
                            const float* __restrict__ b_ih, const float* __restrict__ b_ih_mask,
                            const float* __restrict__ b_hh, const float* __restrict__ b_hh_mask) {
    int i = blockIdx.x * blockDim.x + threadIdx.x;
    if (i < Hh * Ii) {
        float g = hc_gate(w_ih_mask[i]) * w_ih[i];
        __nv_bfloat16 h = __float2bfloat16(g);
        g_wih_hi[i] = h;
        g_wih_lo[i] = __float2bfloat16(g - __bfloat162float(h));
    }
    if (i < Hh) {
        g_bias[i] = hc_gate(b_ih_mask[i]) * b_ih[i] + hc_gate(b_hh_mask[i]) * b_hh[i];
    }
    if (i < 2 * Hh * Bb) g_hT[i] = 0.0f;
    if (i < 128) g_cnt[i] = 0u;
    if (i < XP_BLKS) g_xcnt[i] = 0u;
    if (i == 0) g_done = 0u;
}

// ---------------------------------------------------------------------------
// xproj role on TENSOR pipe (R16 winner, unchanged).
// ---------------------------------------------------------------------------
__device__ void xproj_role(int rtid, int bid, char* xsm, int unit,
                           const float* __restrict__ seq, float* __restrict__ out)
{
    __nv_bfloat16* Ah = (__nv_bfloat16*)xsm;            // [64][24]
    __nv_bfloat16* Al = Ah + 64 * 24;
    __nv_bfloat16* Bh = Al + 64 * 24;                   // [128][16]
    __nv_bfloat16* Bl = Bh + 128 * 16;
    const uint32_t Ah_u = (uint32_t)__cvta_generic_to_shared(Ah);
    const uint32_t Al_u = (uint32_t)__cvta_generic_to_shared(Al);
    const uint32_t Bh_u = (uint32_t)__cvta_generic_to_shared(Bh);
    const uint32_t Bl_u = (uint32_t)__cvta_generic_to_shared(Bl);

    const int w = rtid >> 5;
    const int lane = rtid & 31;
    const int gid = lane >> 2;
    const int tig = lane & 3;

    const uint32_t inv_a = (uint32_t)((((lane & 7) + ((lane >> 3) & 1) * 8) * 48) + ((lane >> 4) * 16));
    const uint32_t inv_b = (uint32_t)(((lane & 7) * 32) + (((lane >> 3) & 1) * 16));

    const int am = rtid >> 1;
    const int ahalf = rtid & 1;
    const int bn = rtid >> 1;
    const int bhalf = rtid & 1;

    for (int tau = unit; tau < XP_TILES; tau += XP_UNITS) {
        const int blk = tau >> 8;
        const int r = tau & 255;
        const int b0 = (r >> 3) << 1;
        const int n0 = (r & 7) << 7;
        const int t0 = blk << 5;

        const float* aptr = seq;
        if (rtid < 128) {
            int mrow = (b0 + (am >> 5)) * Tt + t0 + (am & 31);
            aptr = seq + (size_t)mrow * Ii + ahalf * 8;
        }
        const __nv_bfloat16* bhp = g_wih_hi + (size_t)(n0 + bn) * Ii + bhalf * 8;
        const __nv_bfloat16* blp = g_wih_lo + (size_t)(n0 + bn) * Ii + bhalf * 8;

        float acc[4][2][4];
#pragma unroll
        for (int i = 0; i < 4; i++)
#pragma unroll
            for (int j = 0; j < 2; j++)
#pragma unroll
                for (int q = 0; q < 4; q++) acc[i][j][q] = 0.0f;

        float4 av0, av1;
        if (rtid < 128) { av0 = *(const float4*)(aptr); av1 = *(const float4*)(aptr + 4); }
        uint4 bhv = *(const uint4*)(bhp);
        uint4 blv = *(const uint4*)(blp);

        for (int kt = 0; kt < Ii; kt += 16) {
            if (rtid < 128) {
                uint4 hi4, lo4;
                split8(av0, av1, hi4, lo4);
                *(uint4*)(Ah + am * 24 + ahalf * 8) = hi4;
                *(uint4*)(Al + am * 24 + ahalf * 8) = lo4;
            }
            *(uint4*)(Bh + bn * 16 + bhalf * 8) = bhv;
            *(uint4*)(Bl + bn * 16 + bhalf * 8) = blv;
            BARX(bid);

            if (kt + 16 < Ii) {
                if (rtid < 128) {
                    av0 = *(const float4*)(aptr + kt + 16);
                    av1 = *(const float4*)(aptr + kt + 20);
                }
                bhv = *(const uint4*)(bhp + kt + 16);
                blv = *(const uint4*)(blp + kt + 16);
            }

            uint32_t bhf[2][2], blf[2][2];
#pragma unroll
            for (int nt = 0; nt < 2; nt++) {
                uint32_t boff = (uint32_t)((w * 16 + nt * 8) * 32) + inv_b;
                ldsm_x2(bhf[nt], Bh_u + boff);
                ldsm_x2(blf[nt], Bl_u + boff);
            }
#pragma unroll
            for (int mt = 0; mt < 4; mt++) {
                uint32_t ahf[4], alf[4];
                ldsm_x4(ahf, Ah_u + (uint32_t)(mt * 768) + inv_a);
                ldsm_x4(alf, Al_u + (uint32_t)(mt * 768) + inv_a);
#pragma unroll
                for (int nt = 0; nt < 2; nt++) {
                    mma_bf16(acc[mt][nt], ahf, bhf[nt]);
                    mma_bf16(acc[mt][nt], ahf, blf[nt]);
                    mma_bf16(acc[mt][nt], alf, bhf[nt]);
                }
            }
            BARX(bid);
        }

#pragma unroll
        for (int nt = 0; nt < 2; nt++) {
            int col = n0 + w * 16 + nt * 8 + 2 * tig;
            float2 bv = *(const float2*)&g_bias[col];
#pragma unroll
            for (int mt = 0; mt < 4; mt++) {
                int m0r = mt * 16 + gid;
                int mrow0 = (b0 + (m0r >> 5)) * Tt + t0 + (m0r & 31);
                float2 o0;
                o0.x = acc[mt][nt][0] + bv.x;
                o0.y = acc[mt][nt][1] + bv.y;
                *(float2*)(out + (size_t)mrow0 * Hh + col) = o0;
                int m1r = m0r + 8;
                int mrow1 = (b0 + (m1r >> 5)) * Tt + t0 + (m1r & 31);
                float2 o1;
                o1.x = acc[mt][nt][2] + bv.x;
                o1.y = acc[mt][nt][3] + bv.y;
                *(float2*)(out + (size_t)mrow1 * Hh + col) = o1;
            }
        }
        BARX(bid);
        if (rtid == 0) arrive_release(&g_xcnt[blk]);
    }
}

// ---------------------------------------------------------------------------
// rnn role: R16 compute core; PER-WARP counter polling (lane 0 + syncwarp)
// replaces t0-poll + third block barrier; xcnt gate cached per 32-step block.
// Safety: red reuse guarded by BARX#1/#2 pairing; h double-buffer guarded by
// cnt >= 32*(step+1) before staging (unchanged invariant).
// ---------------------------------------------------------------------------
__device__ void rnn_role(int t, int cta,
                         const float* __restrict__ w_hh, const float* __restrict__ w_hh_mask,
                         float* __restrict__ out, float* sm)
{
    float* Wsh = sm;                    // [1024][32]
    float* hsAll = sm + 32768;          // [8 warps][4 rounds][32 k][16 b]
    float* red = sm + 32768 + 16384;    // [8][16 b][36]

    const int w = t >> 5;
    const int lane = t & 31;
    const int cg = cta >> 2;
    const int bg = cta & 3;
    const int C0 = cg * 32;
    const int B0 = bg * 16;

    for (int i = t; i < 8192; i += 256) {
        int c = i & 31;
        int k4 = (i >> 5) << 2;
        size_t base = (size_t)(C0 + c) * Ii + k4;
        float4 wv = *(const float4*)(w_hh + base);
        float4 mv = *(const float4*)(w_hh_mask + base);
        Wsh[(k4 + 0) * 32 + c] = hc_gate(mv.x) * wv.x;
        Wsh[(k4 + 1) * 32 + c] = hc_gate(mv.y) * wv.y;
        Wsh[(k4 + 2) * 32 + c] = hc_gate(mv.z) * wv.z;
        Wsh[(k4 + 3) * 32 + c] = hc_gate(mv.w) * wv.w;
    }

    const int ksub = lane >> 4;
    const int tile = lane & 15;
    const int cq = tile >> 2;
    const int bq = tile & 3;

    float* hw = hsAll + w * 2048;
    uint32_t hw_u32 = (uint32_t)__cvta_generic_to_shared(hw);
    const int kbase = ((w + cg) & 7) * 128;

    const int c2 = (t & 15) << 1;
    const int b_l = t >> 4;
    const int c_g = C0 + c2;

    unsigned* cnt = &g_cnt[bg * 32];

    int xi = ((B0 + b_l) * Tt) * Hh + c_g;

    // gate x_proj block 0 (per-warp)
    if (lane == 0) {
        while (ld_acquire(&g_xcnt[0]) < XP_TILES_PER_BLK) { }
    }
    __syncwarp();
    BARX(1);   // also orders Wsh staging

    int last_nb = 0;   // xcnt block already verified

    for (int step = 0; step < Tt; step++) {
        const float* hsrc = g_hT + (step & 1) * (Hh * Bb);
        float* hdst = g_hT + ((step & 1) ^ 1) * (Hh * Bb);

#pragma unroll
        for (int r = 0; r < 4; r++) {
#pragma unroll
            for (int i = 0; i < 4; i++) {
                int fid = lane + (i << 5);
                int kk = fid >> 2;
                int c4 = (fid & 3) << 2;
                cpasync16(hw_u32 + ((r * 512 + kk * 16 + c4) << 2),
                          hsrc + (kbase + r * 32 + kk) * Bb + B0 + c4);
            }
            CP_COMMIT();
        }

        float2 xp = *(const float2*)(out + xi);

        u64t acc[4][4];
#pragma unroll
        for (int i = 0; i < 4; i++)
#pragma unroll
            for (int j = 0; j < 4; j++) acc[i][j] = 0ULL;

#pragma unroll
        for (int r = 0; r < 4; r++) {
            switch (r) {
                case 0: asm volatile("cp.async.wait_group 3;"); break;
                case 1: asm volatile("cp.async.wait_group 2;"); break;
                case 2: asm volatile("cp.async.wait_group 1;"); break;
                default: asm volatile("cp.async.wait_group 0;"); break;
            }
            __syncwarp();
            const float* hb = hw + r * 512;
            const int kr = kbase + r * 32;
#pragma unroll
            for (int i = 0; i < 16; i++) {
                int kk = (i << 1) + ksub;
                ulonglong2 wp01 = *(const ulonglong2*)&Wsh[(kr + kk) * 32 + (cq << 3)];
                ulonglong2 wp23 = *(const ulonglong2*)&Wsh[(kr + kk) * 32 + (cq << 3) + 4];
                float4 h4 = *(const float4*)&hb[kk * 16 + (bq << 2)];
                u64t h0 = pack2(h4.x, h4.x);
                u64t h1 = pack2(h4.y, h4.y);
                u64t h2 = pack2(h4.z, h4.z);
                u64t h3 = pack2(h4.w, h4.w);
                acc[0][0] = fma2(wp01.x, h0, acc[0][0]);
                acc[0][1] = fma2(wp01.x, h1, acc[0][1]);
                acc[0][2] = fma2(wp01.x, h2, acc[0][2]);
                acc[0][3] = fma2(wp01.x, h3, acc[0][3]);
                acc[1][0] = fma2(wp01.y, h0, acc[1][0]);
                acc[1][1] = fma2(wp01.y, h1, acc[1][1]);
                acc[1][2] = fma2(wp01.y, h2, acc[1][2]);
                acc[1][3] = fma2(wp01.y, h3, acc[1][3]);
                acc[2][0] = fma2(wp23.x, h0, acc[2][0]);
                acc[2][1] = fma2(wp23.x, h1, acc[2][1]);
                acc[2][2] = fma2(wp23.x, h2, acc[2][2]);
                acc[2][3] = fma2(wp23.x, h3, acc[2][3]);
                acc[3][0] = fma2(wp23.y, h0, acc[3][0]);
                acc[3][1] = fma2(wp23.y, h1, acc[3][1]);
                acc[3][2] = fma2(wp23.y, h2, acc[3][2]);
                acc[3][3] = fma2(wp23.y, h3, acc[3][3]);
            }
        }

#pragma unroll
        for (int cp = 0; cp < 4; cp++)
#pragma unroll
            for (int j = 0; j < 4; j++)
                acc[cp][j] = add2(acc[cp][j],
                                  __shfl_xor_sync(0xFFFFFFFFu, acc[cp][j], 16));

        if (ksub == 0) {
            float* rw = red + w * 576;
#pragma unroll
            for (int j = 0; j < 4; j++) {
                int b_loc = (bq << 2) + j;
#pragma unroll
                for (int cph = 0; cph < 2; cph++) {
                    ulonglong2 v;
                    v.x = acc[2 * cph][j];
                    v.y = acc[2 * cph + 1][j];
                    *(ulonglong2*)&rw[b_loc * 36 + (cq << 3) + (cph << 2)] = v;
                }
            }
        }
        BARX(1);   // #1: partials visible

        float sx = 0.0f, sy = 0.0f;
#pragma unroll
        for (int ww = 0; ww < 8; ww++) {
            float2 v = *(const float2*)&red[ww * 576 + b_l * 36 + c2];
            sx += v.x; sy += v.y;
        }
        float hv0 = tanh_fast(xp.x + sx);
        float hv1 = tanh_fast(xp.y + sy);
        __stcg(hdst + c_g * Bb + B0 + b_l, hv0);
        __stcg(hdst + (c_g + 1) * Bb + B0 + b_l, hv1);

        BARX(1);   // #2: all h stores HB-before t0's release
        if (t == 0 && step < Tt - 1) arrive_release(cnt);

        // out writes overlap the polls
        __stcg((float2*)(out + xi), make_float2(hv0, hv1));
        if (step == Tt - 1) {
            *(float2*)(out + Bb * Tt * Hh + (B0 + b_l) * Hh + c_g) = make_float2(hv0, hv1);
        }
        xi += Hh;

        // per-warp gate for next step (no third block barrier)
        if (step < Tt - 1) {
            int nb = (step + 1) >> 5;
            if (lane == 0) {
                unsigned target = 32u * (unsigned)(step + 1);
                while (ld_acquire(cnt) < target) { }
                if (nb != last_nb) {
                    while (ld_acquire(&g_xcnt[nb]) < XP_TILES_PER_BLK) { }
                }
            }
            last_nb = nb;
            __syncwarp();
        }
    }
}

// ---------------------------------------------------------------------------
// Fused persistent kernel.
// ---------------------------------------------------------------------------
__global__ void __launch_bounds__(512, 1) regrnn_fused(
    const float* __restrict__ seq,
    const float* __restrict__ w_hh, const float* __restrict__ w_hh_mask,
    float* __restrict__ out)
{
    extern __shared__ __align__(16) float sm[];
    const int t = threadIdx.x;
    const int cta = blockIdx.x;
    const int half = t >> 8;
    const int rtid = t & 255;

    char* xsmB = (char*)(sm + RNN_FLOATS);
    char* xsmA = (char*)sm;

    if (cta < FUSED_CTAS) {
        if (half == 0) {
            rnn_role(rtid, cta, w_hh, w_hh_mask, out, sm);
        } else {
            xproj_role(rtid, 2, xsmB, cta, seq, out);
        }
    } else {
        if (half == 0) {
            xproj_role(rtid, 1, xsmA, FUSED_CTAS + (cta - FUSED_CTAS) * 2, seq, out);
        } else {
            xproj_role(rtid, 2, xsmB, FUSED_CTAS + (cta - FUSED_CTAS) * 2 + 1, seq, out);
        }
    }

    // exit protocol: last CTA resets all counters for next graph replay
    if (t == 0) {
        __threadfence();
        unsigned old = atomicAdd(&g_done, 1u);
        if (old == TOTAL_CTAS - 1) {
#pragma unroll 8
            for (int i = 0; i < 128; i++) g_cnt[i] = 0u;
#pragma unroll
            for (int i = 0; i < XP_BLKS; i++) g_xcnt[i] = 0u;
            __threadfence();
            g_done = 0u;
        }
    }
}

// ---------------------------------------------------------------------------
extern "C" void kernel_launch(void* const* d_in, const int* in_sizes, int n_in,
                              void* d_out, int out_size) {
    (void)in_sizes; (void)n_in; (void)out_size;
    const float* seq       = (const float*)d_in[0];
    const float* w_ih      = (const float*)d_in[1];
    const float* w_ih_mask = (const float*)d_in[2];
    const float* w_hh      = (const float*)d_in[3];
    const float* w_hh_mask = (const float*)d_in[4];
    const float* b_ih      = (const float*)d_in[5];
    const float* b_ih_mask = (const float*)d_in[6];
    const float* b_hh      = (const float*)d_in[7];
    const float* b_hh_mask = (const float*)d_in[8];
    float* out = (float*)d_out;

    regrnn_prep<<<(Hh * Ii + 255) / 256, 256>>>(w_ih, w_ih_mask,
                                                b_ih, b_ih_mask, b_hh, b_hh_mask);

    cudaFuncSetAttribute(regrnn_fused, cudaFuncAttributeMaxDynamicSharedMemorySize, SMEM_BYTES);
    regrnn_fused<<<TOTAL_CTAS, 512, SMEM_BYTES>>>(seq, w_hh, w_hh_mask, out);
}